// round 13
// baseline (speedup 1.0000x reference)
#include <cuda_runtime.h>
#include <cstddef>
#include <cstdint>

// HardDTW max-plus scan — cp.async staging + 2-CTA-per-batch K-split.
//
//   out[b,0,k] = x[b,0,k]
//   out[b,t,k] = x[b,t,k] + max(out[b,t-1,k], out[b,t-1,k-1])   (k-1 < 0 -> -inf)
//
// Grid = B*2. CTA (2b+h) owns columns [h*512, h*512+512) of batch b.
// 256 threads (8 warps), thread carries one float2. Warp w of half h is
// pipeline level h*9+w; it processes chunk c = e - level (16 steps) at epoch
// e, one __syncthreads per epoch. x is staged by cp.async (8B/thread/row)
// into double-buffered per-warp smem tiles (no register scoreboards: this is
// what took R12 from 215 -> 174 us); inner loop reads x via LDS.64.
// Intra-CTA edges via double-buffered smem, bulk-loaded into float4 regs per
// chunk (no per-step broadcast shfl). Cross-CTA seam (k=511 -> 512) via gmem
// mailbox + release/acquire flag with a 2-epoch margin (poll normally
// satisfied on arrival); flags zeroed by a graph-ordered init kernel.

namespace {
constexpr int T = 2048;
constexpr int K = 1024;
constexpr int MAXB = 32;
constexpr int THREADS = 256;
constexpr int NWARP = 8;
constexpr int CHUNK = 16;
constexpr int NCHUNK = T / CHUNK;                   // 128
constexpr int CROSS = 9;                            // level of CTA1 warp0
constexpr int NEPOCH = NCHUNK + CROSS + NWARP - 1;  // 144
constexpr int RS2 = K / 2;                          // float2 per full row
constexpr int ROW_BYTES = 32 * 8;                   // 256 B per warp-row
constexpr int SLAB = CHUNK * ROW_BYTES;             // 4 KB per warp per buffer
constexpr size_t SMEM_BYTES = 2u * NWARP * SLAB;    // 64 KB
}

__device__ float eg_edges[MAXB][NCHUNK][CHUNK];     // cross-CTA edge values
__device__ int   eg_flag[MAXB][32];                 // [b][0], padded

__global__ void harddtw_init_kernel() {
    if (threadIdx.x < MAXB) eg_flag[threadIdx.x][0] = 0;
}

__device__ __forceinline__ float bsel(const float4* q, int j) {
    const float4 v = q[j >> 2];
    switch (j & 3) {
        case 0: return v.x;
        case 1: return v.y;
        case 2: return v.z;
        default: return v.w;
    }
}

__global__ __launch_bounds__(THREADS, 1)
void harddtw_split_cpasync_kernel(const float* __restrict__ x,
                                  float* __restrict__ out) {
    extern __shared__ char xs[];                 // [2][NWARP][CHUNK][256B]
    __shared__ __align__(16) float edges[2][NWARP][CHUNK];

    const int tid  = threadIdx.x;
    const int lane = tid & 31;
    const int warp = tid >> 5;
    const int half = blockIdx.x & 1;
    const int b    = blockIdx.x >> 1;
    const int level = half ? (CROSS + warp) : warp;
    const float NI = __int_as_float(0xff800000);

    // This thread's 8B column slice: cols half*512 + tid*2 (+1).
    const char* gbase = reinterpret_cast<const char*>(
        x + (size_t)b * T * K + half * 512 + tid * 2);
    float2* __restrict__ orow =
        reinterpret_cast<float2*>(out + (size_t)b * T * K) + half * 256 + tid;

    const uint32_t s0 = (uint32_t)__cvta_generic_to_shared(xs)
                        + (uint32_t)(warp * SLAB) + (uint32_t)(lane * 8);
    const uint32_t s1 = s0 + (uint32_t)(NWARP * SLAB);

    const bool sprod = (warp < NWARP - 1) && (lane == 31);
    const bool gprod = (half == 0) && (warp == NWARP - 1) && (lane == 31);
    const bool gcons = (half == 1) && (warp == 0);
    const int  pw    = (warp == 0) ? 0 : (warp - 1);
    int* const flagp = &eg_flag[b][0];

    // Prologue: stage chunk 0 into buffer 0.
#pragma unroll
    for (int j = 0; j < CHUNK; ++j) {
        asm volatile("cp.async.ca.shared.global [%0], [%1], 8;"
                     :: "r"(s0 + j * ROW_BYTES),
                        "l"(gbase + (size_t)j * 4096) : "memory");
    }
    asm volatile("cp.async.commit_group;" ::: "memory");

    float2 cur;
    cur.x = NI; cur.y = NI;

    for (int e = 0; e < NEPOCH; ++e) {
        const int c = e - level;
        if (0 <= c && c < NCHUNK) {
            const int t0 = c * CHUNK;
            const uint32_t scur = (c & 1) ? s1 : s0;
            const uint32_t snxt = (c & 1) ? s0 : s1;

            // Stage chunk c+1; wait until chunk c's tile is resident.
            if (c + 1 < NCHUNK) {
                const char* gn = gbase + (size_t)(t0 + CHUNK) * 4096;
#pragma unroll
                for (int j = 0; j < CHUNK; ++j) {
                    asm volatile("cp.async.ca.shared.global [%0], [%1], 8;"
                                 :: "r"(snxt + j * ROW_BYTES),
                                    "l"(gn + (size_t)j * 4096) : "memory");
                }
            }
            asm volatile("cp.async.commit_group;" ::: "memory");
            asm volatile("cp.async.wait_group 1;" ::: "memory");

            // ── Boundary vector into registers (no per-step shfl) ──
            float4 bvq[4];
            if (level == 0) {
#pragma unroll
                for (int i = 0; i < 4; ++i) bvq[i] = make_float4(NI, NI, NI, NI);
            } else if (gcons) {
                int f;
                do {
                    asm volatile("ld.acquire.gpu.global.s32 %0, [%1];"
                                 : "=r"(f) : "l"(flagp) : "memory");
                } while (f < c + 1);
                const float4* src =
                    reinterpret_cast<const float4*>(&eg_edges[b][c][0]);
#pragma unroll
                for (int i = 0; i < 4; ++i) bvq[i] = __ldcg(src + i);
            } else {
                const float4* src =
                    reinterpret_cast<const float4*>(&edges[(e - 1) & 1][pw][0]);
#pragma unroll
                for (int i = 0; i < 4; ++i) bvq[i] = src[i];
            }

            // Publish slot 0: carry entering this chunk (garbage at c==0, unused).
            if (sprod) edges[e & 1][warp][0] = cur.y;
            if (gprod) eg_edges[b][c][0] = cur.y;

#pragma unroll
            for (int j = 0; j < CHUNK; ++j) {
                const int t = t0 + j;
                float2 xv;
                {
                    const uint32_t a = scur + j * ROW_BYTES;
                    asm volatile("ld.shared.v2.f32 {%0,%1}, [%2];"
                                 : "=f"(xv.x), "=f"(xv.y) : "r"(a));
                }

                if (c == 0 && j == 0) {
                    cur = xv;  // init row: out[0] = x[0]
                } else {
                    float up = __shfl_up_sync(0xffffffffu, cur.y, 1);
                    if (lane == 0) up = bsel(bvq, j);   // -inf built in for level 0

                    float2 n;
                    n.x = xv.x + fmaxf(cur.x, up);
                    n.y = xv.y + fmaxf(cur.y, cur.x);
                    cur = n;
                }

                orow[(size_t)t * RS2] = cur;
                if (j < CHUNK - 1) {
                    if (sprod) edges[e & 1][warp][j + 1] = cur.y;
                    if (gprod) eg_edges[b][c][j + 1] = cur.y;
                }
            }

            // Release this chunk's mailbox entries to the consumer CTA.
            if (gprod) {
                int v = c + 1;
                asm volatile("st.release.gpu.global.s32 [%0], %1;"
                             :: "l"(flagp), "r"(v) : "memory");
            }
        }
        __syncthreads();
    }
}

extern "C" void kernel_launch(void* const* d_in, const int* in_sizes, int n_in,
                              void* d_out, int out_size) {
    const float* x = (const float*)d_in[0];
    float* out = (float*)d_out;
    const int B = in_sizes[0] / (T * K);
    harddtw_init_kernel<<<1, 32>>>();
    cudaFuncSetAttribute(harddtw_split_cpasync_kernel,
                         cudaFuncAttributeMaxDynamicSharedMemorySize,
                         (int)SMEM_BYTES);
    harddtw_split_cpasync_kernel<<<B * 2, THREADS, SMEM_BYTES>>>(x, out);
}

// round 14
// speedup vs baseline: 1.5959x; 1.5959x over previous
#include <cuda_runtime.h>
#include <cstddef>
#include <cstdint>

// HardDTW max-plus scan — R12 (cp.async-staged monolithic wavefront) + MIO diet.
//
//   out[b,0,k] = x[b,0,k]
//   out[b,t,k] = x[b,t,k] + max(out[b,t-1,k], out[b,t-1,k-1])   (k-1 < 0 -> -inf)
//
// One CTA per batch (B=32), 256 threads (8 warps), thread owns 4 consecutive k
// (float4 carry). Warp w processes chunk c = e - w (16 steps) at epoch e; one
// __syncthreads per epoch; x staged by cp.async into double-buffered per-warp
// smem tiles (R12: no register scoreboards on the x stream).
// CHANGES vs R12 (MIO-op diet, ~5 -> ~3 MIO ops per warp-step):
//  1. per-step broadcast shfl -> per-chunk bvq[4] registers (4x LDS.128;
//     compile-time select; warp 0 holds -inf constants).
//  2. per-step predicated edge STS -> ew[16] in registers, 4x STS.128 by
//     lane 31 at chunk end (xq no longer register-resident, so no R8 spills).
//  3. output stores use st.global.cs (write-once streaming).

namespace {
constexpr int T = 2048;
constexpr int K = 1024;
constexpr int THREADS = 256;
constexpr int NWARP = THREADS / 32;          // 8
constexpr int RS = K / 4;                    // float4 per row
constexpr int CHUNK = 16;
constexpr int NCHUNK = T / CHUNK;            // 128
constexpr int NEPOCH = NCHUNK + NWARP - 1;   // 135
constexpr int ROW_BYTES = 32 * 16;           // 512 B per warp-row
constexpr int SLAB = CHUNK * ROW_BYTES;      // 8 KB per warp per buffer
constexpr size_t SMEM_BYTES = 2u * NWARP * SLAB;   // 128 KB
}

__device__ __forceinline__ float bsel(const float4* q, int j) {
    const float4 v = q[j >> 2];
    switch (j & 3) {
        case 0: return v.x;
        case 1: return v.y;
        case 2: return v.z;
        default: return v.w;
    }
}

__global__ __launch_bounds__(THREADS, 1)
void harddtw_mio_kernel(const float* __restrict__ x,
                        float* __restrict__ out) {
    extern __shared__ char xs[];               // [2][NWARP][CHUNK][512B]
    __shared__ __align__(16) float edges[2][NWARP][CHUNK];

    const int tid  = threadIdx.x;
    const int lane = tid & 31;
    const int warp = tid >> 5;
    const int b    = blockIdx.x;
    const float NI = __int_as_float(0xff800000);

    // gmem base for this thread's 16B x slice; row r at +r*4096 bytes.
    const char* gbase = reinterpret_cast<const char*>(
        x + (size_t)b * T * K + warp * 128 + lane * 4);
    float4* __restrict__ orow =
        reinterpret_cast<float4*>(out + (size_t)b * T * K) + tid;

    const uint32_t s0 = (uint32_t)__cvta_generic_to_shared(xs)
                        + (uint32_t)(warp * SLAB) + (uint32_t)(lane * 16);
    const uint32_t s1 = s0 + (uint32_t)(NWARP * SLAB);

    const bool prod = (warp < NWARP - 1) && (lane == 31);
    const int pw = (warp == 0) ? 0 : (warp - 1);

    // Prologue: stage chunk 0 into buffer 0.
#pragma unroll
    for (int j = 0; j < CHUNK; ++j) {
        asm volatile("cp.async.cg.shared.global [%0], [%1], 16;"
                     :: "r"(s0 + j * ROW_BYTES),
                        "l"(gbase + (size_t)j * 4096) : "memory");
    }
    asm volatile("cp.async.commit_group;" ::: "memory");

    float4 cur = make_float4(NI, NI, NI, NI);

    for (int e = 0; e < NEPOCH; ++e) {
        const int c = e - warp;
        if (0 <= c && c < NCHUNK) {
            const int t0 = c * CHUNK;
            const uint32_t scur = (c & 1) ? s1 : s0;
            const uint32_t snxt = (c & 1) ? s0 : s1;

            // Stage chunk c+1; wait until chunk c's tile is resident.
            if (c + 1 < NCHUNK) {
                const char* gn = gbase + (size_t)(t0 + CHUNK) * 4096;
#pragma unroll
                for (int j = 0; j < CHUNK; ++j) {
                    asm volatile("cp.async.cg.shared.global [%0], [%1], 16;"
                                 :: "r"(snxt + j * ROW_BYTES),
                                    "l"(gn + (size_t)j * 4096) : "memory");
                }
            }
            asm volatile("cp.async.commit_group;" ::: "memory");
            asm volatile("cp.async.wait_group 1;" ::: "memory");

            // ── Boundary vector into registers (kills per-step broadcast shfl) ──
            float4 bvq[4];
            if (warp == 0) {
#pragma unroll
                for (int i = 0; i < 4; ++i) bvq[i] = make_float4(NI, NI, NI, NI);
            } else {
                const float4* src =
                    reinterpret_cast<const float4*>(&edges[(e - 1) & 1][pw][0]);
#pragma unroll
                for (int i = 0; i < 4; ++i) bvq[i] = src[i];
            }

            // Edge values to publish at chunk end: ew[s] = out[t0+s-1].w.
            float ew[CHUNK];
            ew[0] = cur.w;          // carry entering this chunk

            float4* op = orow + (size_t)t0 * RS;

#pragma unroll
            for (int j = 0; j < CHUNK; ++j) {
                float4 xv;
                {
                    const uint32_t a = scur + j * ROW_BYTES;
                    asm volatile("ld.shared.v4.f32 {%0,%1,%2,%3}, [%4];"
                                 : "=f"(xv.x), "=f"(xv.y), "=f"(xv.z), "=f"(xv.w)
                                 : "r"(a));
                }

                if (c == 0 && j == 0) {
                    cur = xv;  // init row: out[0] = x[0]
                } else {
                    float up = __shfl_up_sync(0xffffffffu, cur.w, 1);
                    if (lane == 0) up = bsel(bvq, j);   // -inf built in for warp 0

                    float4 n;
                    n.x = xv.x + fmaxf(cur.x, up);
                    n.y = xv.y + fmaxf(cur.y, cur.x);
                    n.z = xv.z + fmaxf(cur.z, cur.y);
                    n.w = xv.w + fmaxf(cur.w, cur.z);
                    cur = n;
                }

                // Streaming store (write-once output, evict-first).
                asm volatile("st.global.cs.v4.f32 [%0], {%1,%2,%3,%4};"
                             :: "l"(op + (size_t)j * RS),
                                "f"(cur.x), "f"(cur.y), "f"(cur.z), "f"(cur.w)
                             : "memory");

                if (j < CHUNK - 1) ew[j + 1] = cur.w;
            }

            // Batched edge publish: 4x STS.128 by lane 31 of warps 0..6.
            if (prod) {
                float4* dst = reinterpret_cast<float4*>(&edges[e & 1][warp][0]);
                dst[0] = make_float4(ew[0],  ew[1],  ew[2],  ew[3]);
                dst[1] = make_float4(ew[4],  ew[5],  ew[6],  ew[7]);
                dst[2] = make_float4(ew[8],  ew[9],  ew[10], ew[11]);
                dst[3] = make_float4(ew[12], ew[13], ew[14], ew[15]);
            }
        }
        __syncthreads();
    }
}

extern "C" void kernel_launch(void* const* d_in, const int* in_sizes, int n_in,
                              void* d_out, int out_size) {
    const float* x = (const float*)d_in[0];
    float* out = (float*)d_out;
    const int B = in_sizes[0] / (T * K);
    cudaFuncSetAttribute(harddtw_mio_kernel,
                         cudaFuncAttributeMaxDynamicSharedMemorySize,
                         (int)SMEM_BYTES);
    harddtw_mio_kernel<<<B, THREADS, SMEM_BYTES>>>(x, out);
}

// round 15
// speedup vs baseline: 1.6283x; 1.0203x over previous
#include <cuda_runtime.h>
#include <cuda.h>
#include <cstddef>
#include <cstdint>

// HardDTW max-plus scan — R14 wavefront with TMA-staged x tiles.
//
//   out[b,0,k] = x[b,0,k]
//   out[b,t,k] = x[b,t,k] + max(out[b,t-1,k], out[b,t-1,k-1])   (k-1 < 0 -> -inf)
//
// One CTA per batch (B=32), 256 threads (8 warps), thread owns 4 consecutive k.
// Warp w processes chunk c = e - w (16 steps) at epoch e; one __syncthreads
// per epoch; edges double-buffered in smem, bulk-read into bvq registers and
// bulk-published (R14). CHANGE vs R14: the cp.async staging (16 LDGSTS ops x
// 8 cyc LSU issue per warp-chunk = 1024 cyc/SM/epoch) is replaced by ONE TMA
// 2D load per warp-chunk (box [128 floats x 16 rows] = 8 KB) completing on a
// per-warp mbarrier. TMA issues on the TMA unit, not the LSU — per-SM LSU
// issue cost (the measured binder) drops ~2550 -> ~2000 cyc/epoch.

namespace {
constexpr int T = 2048;
constexpr int K = 1024;
constexpr int THREADS = 256;
constexpr int NWARP = THREADS / 32;          // 8
constexpr int RS = K / 4;                    // float4 per row
constexpr int CHUNK = 16;
constexpr int NCHUNK = T / CHUNK;            // 128
constexpr int NEPOCH = NCHUNK + NWARP - 1;   // 135
constexpr int ROW_BYTES = 32 * 16;           // 512 B per warp-row
constexpr int SLAB = CHUNK * ROW_BYTES;      // 8 KB per warp per buffer
constexpr size_t SMEM_BYTES = 2u * NWARP * SLAB;   // 128 KB dynamic
}

__device__ __forceinline__ float bsel(const float4* q, int j) {
    const float4 v = q[j >> 2];
    switch (j & 3) {
        case 0: return v.x;
        case 1: return v.y;
        case 2: return v.z;
        default: return v.w;
    }
}

// ───────────────────────── TMA-load kernel ─────────────────────────
__global__ __launch_bounds__(THREADS, 1)
void harddtw_tmald_kernel(const __grid_constant__ CUtensorMap tmap,
                          float* __restrict__ out) {
    extern __shared__ char xs[];                 // [2][NWARP][CHUNK][512B]
    __shared__ __align__(16) float edges[2][NWARP][CHUNK];
    __shared__ __align__(8) uint64_t mbar[NWARP][2];   // per warp, per buffer

    const int tid  = threadIdx.x;
    const int lane = tid & 31;
    const int warp = tid >> 5;
    const int b    = blockIdx.x;
    const float NI = __int_as_float(0xff800000);

    float4* __restrict__ orow =
        reinterpret_cast<float4*>(out + (size_t)b * T * K) + tid;

    // slab(s): base smem address of this warp's buffer s.
    const uint32_t slab0 = (uint32_t)__cvta_generic_to_shared(xs)
                           + (uint32_t)(warp * SLAB);
    const uint32_t slab1 = slab0 + (uint32_t)(NWARP * SLAB);
    const uint32_t mb0 = (uint32_t)__cvta_generic_to_shared(&mbar[warp][0]);
    const uint32_t mb1 = (uint32_t)__cvta_generic_to_shared(&mbar[warp][1]);

    const bool prod = (warp < NWARP - 1) && (lane == 31);
    const int pw = (warp == 0) ? 0 : (warp - 1);
    const int x0 = warp * 128;                   // element coord in K

    // Init mbarriers (count 1; completion is transaction-based).
    if (tid < NWARP * 2) {
        uint32_t a = (uint32_t)__cvta_generic_to_shared(&mbar[tid >> 1][tid & 1]);
        asm volatile("mbarrier.init.shared.b64 [%0], 1;" :: "r"(a) : "memory");
    }
    __syncthreads();

    // Prologue: stage chunk 0 into buffer 0 (every warp, lane 0).
    if (lane == 0) {
        asm volatile("mbarrier.arrive.expect_tx.shared.b64 _, [%0], %1;"
                     :: "r"(mb0), "r"((uint32_t)SLAB) : "memory");
        asm volatile(
            "cp.async.bulk.tensor.2d.shared::cta.global.tile"
            ".mbarrier::complete_tx::bytes [%0], [%1, {%2, %3}], [%4];"
            :: "r"(slab0), "l"(&tmap), "r"(x0), "r"(b * T), "r"(mb0) : "memory");
    }

    float4 cur = make_float4(NI, NI, NI, NI);

    for (int e = 0; e < NEPOCH; ++e) {
        const int c = e - warp;
        if (0 <= c && c < NCHUNK) {
            const int t0 = c * CHUNK;
            const uint32_t scur = (c & 1) ? slab1 : slab0;
            const uint32_t mcur = (c & 1) ? mb1 : mb0;

            // Issue TMA for chunk c+1 into the other buffer (its previous
            // occupant, chunk c-1, was fully consumed by this warp last epoch).
            if (lane == 0 && c + 1 < NCHUNK) {
                const uint32_t snxt = (c & 1) ? slab0 : slab1;
                const uint32_t mnxt = (c & 1) ? mb0 : mb1;
                asm volatile("fence.proxy.async.shared::cta;" ::: "memory");
                asm volatile("mbarrier.arrive.expect_tx.shared.b64 _, [%0], %1;"
                             :: "r"(mnxt), "r"((uint32_t)SLAB) : "memory");
                asm volatile(
                    "cp.async.bulk.tensor.2d.shared::cta.global.tile"
                    ".mbarrier::complete_tx::bytes [%0], [%1, {%2, %3}], [%4];"
                    :: "r"(snxt), "l"(&tmap), "r"(x0),
                       "r"(b * T + t0 + CHUNK), "r"(mnxt) : "memory");
            }

            // Wait for chunk c's tile (parity = (c>>1)&1).
            {
                const uint32_t par = (uint32_t)((c >> 1) & 1);
                uint32_t done;
                asm volatile(
                    "{\n\t.reg .pred p;\n\t"
                    "mbarrier.try_wait.parity.acquire.cta.shared::cta.b64 p, [%1], %2;\n\t"
                    "selp.b32 %0, 1, 0, p;\n\t}"
                    : "=r"(done) : "r"(mcur), "r"(par) : "memory");
                while (!done) {
                    asm volatile(
                        "{\n\t.reg .pred p;\n\t"
                        "mbarrier.try_wait.parity.acquire.cta.shared::cta.b64 p, [%1], %2, 0x989680;\n\t"
                        "selp.b32 %0, 1, 0, p;\n\t}"
                        : "=r"(done) : "r"(mcur), "r"(par) : "memory");
                }
            }

            // Boundary vector into registers (R14).
            float4 bvq[4];
            if (warp == 0) {
#pragma unroll
                for (int i = 0; i < 4; ++i) bvq[i] = make_float4(NI, NI, NI, NI);
            } else {
                const float4* src =
                    reinterpret_cast<const float4*>(&edges[(e - 1) & 1][pw][0]);
#pragma unroll
                for (int i = 0; i < 4; ++i) bvq[i] = src[i];
            }

            float ew[CHUNK];
            ew[0] = cur.w;
            float4* op = orow + (size_t)t0 * RS;
            const uint32_t lbase = scur + (uint32_t)(lane * 16);

#pragma unroll
            for (int j = 0; j < CHUNK; ++j) {
                float4 xv;
                asm volatile("ld.shared.v4.f32 {%0,%1,%2,%3}, [%4];"
                             : "=f"(xv.x), "=f"(xv.y), "=f"(xv.z), "=f"(xv.w)
                             : "r"(lbase + j * ROW_BYTES));

                if (c == 0 && j == 0) {
                    cur = xv;  // init row: out[0] = x[0]
                } else {
                    float up = __shfl_up_sync(0xffffffffu, cur.w, 1);
                    if (lane == 0) up = bsel(bvq, j);

                    float4 n;
                    n.x = xv.x + fmaxf(cur.x, up);
                    n.y = xv.y + fmaxf(cur.y, cur.x);
                    n.z = xv.z + fmaxf(cur.z, cur.y);
                    n.w = xv.w + fmaxf(cur.w, cur.z);
                    cur = n;
                }

                asm volatile("st.global.cs.v4.f32 [%0], {%1,%2,%3,%4};"
                             :: "l"(op + (size_t)j * RS),
                                "f"(cur.x), "f"(cur.y), "f"(cur.z), "f"(cur.w)
                             : "memory");

                if (j < CHUNK - 1) ew[j + 1] = cur.w;
            }

            if (prod) {
                float4* dst = reinterpret_cast<float4*>(&edges[e & 1][warp][0]);
                dst[0] = make_float4(ew[0],  ew[1],  ew[2],  ew[3]);
                dst[1] = make_float4(ew[4],  ew[5],  ew[6],  ew[7]);
                dst[2] = make_float4(ew[8],  ew[9],  ew[10], ew[11]);
                dst[3] = make_float4(ew[12], ew[13], ew[14], ew[15]);
            }
        }
        __syncthreads();
    }
}

// ───────────────────── fallback: R14 cp.async kernel ─────────────────────
__global__ __launch_bounds__(THREADS, 1)
void harddtw_mio_kernel(const float* __restrict__ x,
                        float* __restrict__ out) {
    extern __shared__ char xs[];
    __shared__ __align__(16) float edges[2][NWARP][CHUNK];

    const int tid  = threadIdx.x;
    const int lane = tid & 31;
    const int warp = tid >> 5;
    const int b    = blockIdx.x;
    const float NI = __int_as_float(0xff800000);

    const char* gbase = reinterpret_cast<const char*>(
        x + (size_t)b * T * K + warp * 128 + lane * 4);
    float4* __restrict__ orow =
        reinterpret_cast<float4*>(out + (size_t)b * T * K) + tid;

    const uint32_t s0 = (uint32_t)__cvta_generic_to_shared(xs)
                        + (uint32_t)(warp * SLAB) + (uint32_t)(lane * 16);
    const uint32_t s1 = s0 + (uint32_t)(NWARP * SLAB);

    const bool prod = (warp < NWARP - 1) && (lane == 31);
    const int pw = (warp == 0) ? 0 : (warp - 1);

#pragma unroll
    for (int j = 0; j < CHUNK; ++j) {
        asm volatile("cp.async.cg.shared.global [%0], [%1], 16;"
                     :: "r"(s0 + j * ROW_BYTES),
                        "l"(gbase + (size_t)j * 4096) : "memory");
    }
    asm volatile("cp.async.commit_group;" ::: "memory");

    float4 cur = make_float4(NI, NI, NI, NI);

    for (int e = 0; e < NEPOCH; ++e) {
        const int c = e - warp;
        if (0 <= c && c < NCHUNK) {
            const int t0 = c * CHUNK;
            const uint32_t scur = (c & 1) ? s1 : s0;
            const uint32_t snxt = (c & 1) ? s0 : s1;

            if (c + 1 < NCHUNK) {
                const char* gn = gbase + (size_t)(t0 + CHUNK) * 4096;
#pragma unroll
                for (int j = 0; j < CHUNK; ++j) {
                    asm volatile("cp.async.cg.shared.global [%0], [%1], 16;"
                                 :: "r"(snxt + j * ROW_BYTES),
                                    "l"(gn + (size_t)j * 4096) : "memory");
                }
            }
            asm volatile("cp.async.commit_group;" ::: "memory");
            asm volatile("cp.async.wait_group 1;" ::: "memory");

            float4 bvq[4];
            if (warp == 0) {
#pragma unroll
                for (int i = 0; i < 4; ++i) bvq[i] = make_float4(NI, NI, NI, NI);
            } else {
                const float4* src =
                    reinterpret_cast<const float4*>(&edges[(e - 1) & 1][pw][0]);
#pragma unroll
                for (int i = 0; i < 4; ++i) bvq[i] = src[i];
            }

            float ew[CHUNK];
            ew[0] = cur.w;
            float4* op = orow + (size_t)t0 * RS;

#pragma unroll
            for (int j = 0; j < CHUNK; ++j) {
                float4 xv;
                asm volatile("ld.shared.v4.f32 {%0,%1,%2,%3}, [%4];"
                             : "=f"(xv.x), "=f"(xv.y), "=f"(xv.z), "=f"(xv.w)
                             : "r"(scur + j * ROW_BYTES));

                if (c == 0 && j == 0) {
                    cur = xv;
                } else {
                    float up = __shfl_up_sync(0xffffffffu, cur.w, 1);
                    if (lane == 0) up = bsel(bvq, j);

                    float4 n;
                    n.x = xv.x + fmaxf(cur.x, up);
                    n.y = xv.y + fmaxf(cur.y, cur.x);
                    n.z = xv.z + fmaxf(cur.z, cur.y);
                    n.w = xv.w + fmaxf(cur.w, cur.z);
                    cur = n;
                }

                asm volatile("st.global.cs.v4.f32 [%0], {%1,%2,%3,%4};"
                             :: "l"(op + (size_t)j * RS),
                                "f"(cur.x), "f"(cur.y), "f"(cur.z), "f"(cur.w)
                             : "memory");

                if (j < CHUNK - 1) ew[j + 1] = cur.w;
            }

            if (prod) {
                float4* dst = reinterpret_cast<float4*>(&edges[e & 1][warp][0]);
                dst[0] = make_float4(ew[0],  ew[1],  ew[2],  ew[3]);
                dst[1] = make_float4(ew[4],  ew[5],  ew[6],  ew[7]);
                dst[2] = make_float4(ew[8],  ew[9],  ew[10], ew[11]);
                dst[3] = make_float4(ew[12], ew[13], ew[14], ew[15]);
            }
        }
        __syncthreads();
    }
}

// ───────────────────────── host ─────────────────────────
typedef CUresult (*PFN_EncodeTiled)(
    CUtensorMap*, CUtensorMapDataType, cuuint32_t, void*,
    const cuuint64_t*, const cuuint64_t*, const cuuint32_t*, const cuuint32_t*,
    CUtensorMapInterleave, CUtensorMapSwizzle, CUtensorMapL2promotion,
    CUtensorMapFloatOOBfill);

extern "C" void kernel_launch(void* const* d_in, const int* in_sizes, int n_in,
                              void* d_out, int out_size) {
    const float* x = (const float*)d_in[0];
    float* out = (float*)d_out;
    const int B = in_sizes[0] / (T * K);

    bool tma_ok = false;
    CUtensorMap tmap;
    {
        void* fp = nullptr;
        cudaDriverEntryPointQueryResult st;
        if (cudaGetDriverEntryPointByVersion("cuTensorMapEncodeTiled", &fp, 12000,
                                             cudaEnableDefault, &st) == cudaSuccess
            && fp && st == cudaDriverEntryPointSuccess) {
            PFN_EncodeTiled enc = (PFN_EncodeTiled)fp;
            cuuint64_t dims[2]    = {(cuuint64_t)K, (cuuint64_t)((size_t)B * T)};
            cuuint64_t strides[1] = {(cuuint64_t)K * sizeof(float)};
            cuuint32_t box[2]     = {128u, (cuuint32_t)CHUNK};
            cuuint32_t estr[2]    = {1u, 1u};
            CUresult r = enc(&tmap, CU_TENSOR_MAP_DATA_TYPE_FLOAT32, 2,
                             const_cast<float*>(x),
                             dims, strides, box, estr,
                             CU_TENSOR_MAP_INTERLEAVE_NONE,
                             CU_TENSOR_MAP_SWIZZLE_NONE,
                             CU_TENSOR_MAP_L2_PROMOTION_L2_128B,
                             CU_TENSOR_MAP_FLOAT_OOB_FILL_NONE);
            tma_ok = (r == CUDA_SUCCESS);
        }
    }

    if (tma_ok) {
        cudaFuncSetAttribute(harddtw_tmald_kernel,
                             cudaFuncAttributeMaxDynamicSharedMemorySize,
                             (int)SMEM_BYTES);
        harddtw_tmald_kernel<<<B, THREADS, SMEM_BYTES>>>(tmap, out);
    } else {
        cudaFuncSetAttribute(harddtw_mio_kernel,
                             cudaFuncAttributeMaxDynamicSharedMemorySize,
                             (int)SMEM_BYTES);
        harddtw_mio_kernel<<<B, THREADS, SMEM_BYTES>>>(x, out);
    }
}